// round 1
// baseline (speedup 1.0000x reference)
#include <cuda_runtime.h>

#define MAX_NODES 100000
#define INDIM 128
#define HID 64

// Scratch: per-node projections P[n][0:64]=z@W1a + b1, P[n][64:128]=z@W1b
__device__ float g_P[MAX_NODES * 128];
__device__ int g_is64;

// ---------------------------------------------------------------------------
// Detect whether edge_index is int64 or int32.
// If int64 (little-endian, values in [0,100000)), the odd int32 words are the
// zero high-halves. If int32, they are random edge indices (P[all 64 zero]≈0).
__global__ void detect_kernel(const int* __restrict__ ei) {
    int s = 0;
#pragma unroll
    for (int k = 0; k < 64; k++) s |= ei[2 * k + 1];
    g_is64 = (s == 0) ? 1 : 0;
}

// ---------------------------------------------------------------------------
// Precompute GEMM: P[100K,128] = z[100K,128] @ Wcat[128,128]  (+ b1 on cols 0..63)
// Wcat[k][o] = (o<64) ? W1[k][o] : W1[128+k][o-64]
// Block: 256 threads computes 128 nodes x 128 cols. Per-thread 8x8 register tile.
// K processed in 4 chunks of 32; z chunk stored k-major (transposed) in smem so
// the A fragment is two LDS.128 per k.
__global__ __launch_bounds__(256) void precompute_kernel(
    const float* __restrict__ z, const float* __restrict__ W1,
    const float* __restrict__ b1, int n_nodes)
{
    __shared__ __align__(16) float zs[32 * 132];  // [k_local][node], node-stride 132
    __shared__ __align__(16) float ws[32 * 128];  // [k_local][col]

    const int tid = threadIdx.x;
    const int g   = tid >> 4;     // node group 0..15  -> nodes g*8 .. g*8+7
    const int c   = tid & 15;     // col group  0..15  -> cols  c*8 .. c*8+7
    const int c0  = c * 8;
    const int nb  = blockIdx.x * 128;

    float acc[8][8];
#pragma unroll
    for (int i = 0; i < 8; i++)
#pragma unroll
        for (int j = 0; j < 8; j++) acc[i][j] = 0.f;

    for (int kc = 0; kc < 4; kc++) {
        __syncthreads();
        // z chunk, transposed: zs[kq][n] = z[nb+n][kc*32+kq]
        for (int idx = tid; idx < 128 * 32; idx += 256) {
            int n  = idx >> 5;
            int kq = idx & 31;
            int row = nb + n;
            float v = (row < n_nodes) ? z[(size_t)row * 128 + kc * 32 + kq] : 0.f;
            zs[kq * 132 + n] = v;
        }
        // W chunk: ws[kl][o]
        for (int idx = tid; idx < 32 * 128; idx += 256) {
            int kl = idx >> 7;
            int o  = idx & 127;
            int kk = kc * 32 + kl;
            float wv = (o < 64) ? W1[kk * 64 + o] : W1[(128 + kk) * 64 + (o - 64)];
            ws[idx] = wv;
        }
        __syncthreads();

#pragma unroll
        for (int k = 0; k < 32; k++) {
            float4 a0  = *(const float4*)&zs[k * 132 + g * 8];
            float4 a1  = *(const float4*)&zs[k * 132 + g * 8 + 4];
            float4 bv0 = *(const float4*)&ws[k * 128 + c0];
            float4 bv1 = *(const float4*)&ws[k * 128 + c0 + 4];
            float a[8] = {a0.x, a0.y, a0.z, a0.w, a1.x, a1.y, a1.z, a1.w};
            float b[8] = {bv0.x, bv0.y, bv0.z, bv0.w, bv1.x, bv1.y, bv1.z, bv1.w};
#pragma unroll
            for (int i = 0; i < 8; i++)
#pragma unroll
                for (int j = 0; j < 8; j++)
                    acc[i][j] = fmaf(a[i], b[j], acc[i][j]);
        }
    }

    // fold b1 into the PA half (cols < 64)
    float bias[8];
#pragma unroll
    for (int j = 0; j < 8; j++) bias[j] = (c0 < 64) ? b1[c0 + j] : 0.f;

#pragma unroll
    for (int i = 0; i < 8; i++) {
        int row = nb + g * 8 + i;
        if (row < n_nodes) {
            float4 o0 = make_float4(acc[i][0] + bias[0], acc[i][1] + bias[1],
                                    acc[i][2] + bias[2], acc[i][3] + bias[3]);
            float4 o1 = make_float4(acc[i][4] + bias[4], acc[i][5] + bias[5],
                                    acc[i][6] + bias[6], acc[i][7] + bias[7]);
            *(float4*)&g_P[(size_t)row * 128 + c0]     = o0;
            *(float4*)&g_P[(size_t)row * 128 + c0 + 4] = o1;
        }
    }
}

// ---------------------------------------------------------------------------
__device__ __forceinline__ int load_idx(const void* eidx, bool is64, long long off) {
    return is64 ? (int)((const long long*)eidx)[off] : ((const int*)eidx)[off];
}

// Edge kernel: warp per edge (grid-strided). Each lane holds one W2 column in
// 64 registers; h1 (64 floats) is shared per-warp via smem and read back as
// float4 broadcasts. 2-deep pipeline: P rows prefetched one edge ahead,
// indices two edges ahead, to hide L2/DRAM latency.
__global__ __launch_bounds__(256) void edge_kernel(
    const void* __restrict__ eidx,
    const float* __restrict__ W2, const float* __restrict__ b2,
    const float* __restrict__ W3, const float* __restrict__ b3,
    float* __restrict__ out, int E)
{
    __shared__ __align__(16) float h1s[8][64];
    const int lane = threadIdx.x & 31;
    const int wid  = threadIdx.x >> 5;
    const int gw   = (blockIdx.x * blockDim.x + threadIdx.x) >> 5;
    const int GW   = (gridDim.x * blockDim.x) >> 5;
    const bool is64 = (g_is64 != 0);

    // per-lane weight column
    float w2r[64];
#pragma unroll
    for (int k = 0; k < 64; k++) w2r[k] = W2[k * 32 + lane];
    const float b2r = b2[lane];
    const float w3r = W3[lane];
    const float b3v = b3[0];

    const float* __restrict__ P = g_P;

    int e = gw;
    int i0 = 0, j0 = 0;
    if (e < E) { i0 = load_idx(eidx, is64, e); j0 = load_idx(eidx, is64, (long long)E + e); }
    const float* pi = P + (size_t)i0 * 128;
    const float* pj = P + (size_t)j0 * 128 + 64;
    float pa0 = pi[lane], pa1 = pi[lane + 32];
    float pb0 = pj[lane], pb1 = pj[lane + 32];

    int en = e + GW;
    int i1 = 0, j1 = 0;
    if (en < E) { i1 = load_idx(eidx, is64, en); j1 = load_idx(eidx, is64, (long long)E + en); }

    while (e < E) {
        // prefetch P rows for next edge
        const float* pin = P + (size_t)i1 * 128;
        const float* pjn = P + (size_t)j1 * 128 + 64;
        float npa0 = pin[lane], npa1 = pin[lane + 32];
        float npb0 = pjn[lane], npb1 = pjn[lane + 32];
        // prefetch indices two ahead
        int e2 = en + GW;
        int i2 = 0, j2 = 0;
        if (e2 < E) { i2 = load_idx(eidx, is64, e2); j2 = load_idx(eidx, is64, (long long)E + e2); }

        // layer 1 (gather + add + relu); b1 already folded into P's PA half
        float h1a = fmaxf(pa0 + pb0, 0.f);
        float h1b = fmaxf(pa1 + pb1, 0.f);
        h1s[wid][lane]      = h1a;
        h1s[wid][lane + 32] = h1b;
        __syncwarp();

        // layer 2: h2[lane] = relu(b2[lane] + sum_k h1[k] * W2[k][lane])
        float acc = b2r;
        const float4* hp = (const float4*)h1s[wid];
#pragma unroll
        for (int k4 = 0; k4 < 16; k4++) {
            float4 h = hp[k4];
            acc = fmaf(h.x, w2r[4 * k4 + 0], acc);
            acc = fmaf(h.y, w2r[4 * k4 + 1], acc);
            acc = fmaf(h.z, w2r[4 * k4 + 2], acc);
            acc = fmaf(h.w, w2r[4 * k4 + 3], acc);
        }
        __syncwarp();

        // layer 3 + sigmoid
        float h2 = fmaxf(acc, 0.f);
        float p  = h2 * w3r;
        p += __shfl_xor_sync(0xffffffffu, p, 16);
        p += __shfl_xor_sync(0xffffffffu, p, 8);
        p += __shfl_xor_sync(0xffffffffu, p, 4);
        p += __shfl_xor_sync(0xffffffffu, p, 2);
        p += __shfl_xor_sync(0xffffffffu, p, 1);
        if (lane == 0) {
            float logit = p + b3v;
            out[e] = __fdividef(1.f, 1.f + __expf(-logit));
        }

        // rotate pipeline
        pa0 = npa0; pa1 = npa1; pb0 = npb0; pb1 = npb1;
        i1 = i2; j1 = j2;
        e = en; en = e2;
    }
}

// ---------------------------------------------------------------------------
extern "C" void kernel_launch(void* const* d_in, const int* in_sizes, int n_in,
                              void* d_out, int out_size)
{
    const float* z  = (const float*)d_in[0];
    const void*  ei = d_in[1];
    const float* W1 = (const float*)d_in[2];
    const float* b1 = (const float*)d_in[3];
    const float* W2 = (const float*)d_in[4];
    const float* b2 = (const float*)d_in[5];
    const float* W3 = (const float*)d_in[6];
    const float* b3 = (const float*)d_in[7];
    float* out = (float*)d_out;

    int n_nodes = in_sizes[0] / INDIM;
    if (n_nodes > MAX_NODES) n_nodes = MAX_NODES;
    int E = out_size;  // one output per edge

    detect_kernel<<<1, 1>>>((const int*)ei);
    int gblocks = (n_nodes + 127) / 128;
    precompute_kernel<<<gblocks, 256>>>(z, W1, b1, n_nodes);
    edge_kernel<<<1184, 256>>>(ei, W2, b2, W3, b3, out, E);
}

// round 2
// speedup vs baseline: 1.0428x; 1.0428x over previous
#include <cuda_runtime.h>

#define MAX_NODES 100000
#define INDIM 128
#define HID 64

// Scratch: per-node projections P[n][0:64]=z@W1a + b1, P[n][64:128]=z@W1b
__device__ float g_P[MAX_NODES * 128];

// ---------------------------------------------------------------------------
// f32x2 packed helpers (Blackwell FFMA2 — ptxas won't auto-fuse, PTX only)
__device__ __forceinline__ unsigned long long pack2(float lo, float hi) {
    unsigned long long r;
    asm("mov.b64 %0, {%1, %2};" : "=l"(r) : "f"(lo), "f"(hi));
    return r;
}
__device__ __forceinline__ void unpack2(unsigned long long v, float& lo, float& hi) {
    asm("mov.b64 {%0, %1}, %2;" : "=f"(lo), "=f"(hi) : "l"(v));
}
__device__ __forceinline__ void ffma2(unsigned long long& d, unsigned long long a,
                                      unsigned long long b) {
    asm("fma.rn.f32x2 %0, %1, %2, %0;" : "+l"(d) : "l"(a), "l"(b));
}

// ---------------------------------------------------------------------------
// Precompute GEMM: P[100K,128] = z[100K,128] @ Wcat[128,128]  (+ b1 on cols 0..63)
// Wcat[k][o] = (o<64) ? W1[k][o] : W1[128+k][o-64]
// 256 threads -> 128 nodes x 128 cols; per-thread 8 rows x 8 cols, accumulated
// as f32x2 pairs along the column dim (32 FFMA2 + 8 MOV64 per k instead of 64 FFMA).
__global__ __launch_bounds__(256) void precompute_kernel(
    const float* __restrict__ z, const float* __restrict__ W1,
    const float* __restrict__ b1, int n_nodes)
{
    __shared__ __align__(16) float zs[32 * 132];  // [k_local][node], node-stride 132
    __shared__ __align__(16) float ws[32 * 128];  // [k_local][col]

    const int tid = threadIdx.x;
    const int g   = tid >> 4;     // node group 0..15  -> rows g*8..g*8+7
    const int c   = tid & 15;     // col group  0..15  -> cols c*8..c*8+7
    const int c0  = c * 8;
    const int nb  = blockIdx.x * 128;

    unsigned long long acc2[8][4];  // [row][col-pair]
#pragma unroll
    for (int i = 0; i < 8; i++)
#pragma unroll
        for (int j = 0; j < 4; j++) acc2[i][j] = 0ull;

    for (int kc = 0; kc < 4; kc++) {
        __syncthreads();
        // z chunk, transposed: zs[kq][n] = z[nb+n][kc*32+kq]
        for (int idx = tid; idx < 128 * 32; idx += 256) {
            int n  = idx >> 5;
            int kq = idx & 31;
            int row = nb + n;
            float v = (row < n_nodes) ? z[(size_t)row * 128 + kc * 32 + kq] : 0.f;
            zs[kq * 132 + n] = v;
        }
        // W chunk: ws[kl][o]
        for (int idx = tid; idx < 32 * 128; idx += 256) {
            int kl = idx >> 7;
            int o  = idx & 127;
            int kk = kc * 32 + kl;
            float wv = (o < 64) ? W1[kk * 64 + o] : W1[(128 + kk) * 64 + (o - 64)];
            ws[idx] = wv;
        }
        __syncthreads();

#pragma unroll
        for (int k = 0; k < 32; k++) {
            float4 a0 = *(const float4*)&zs[k * 132 + g * 8];
            float4 a1 = *(const float4*)&zs[k * 132 + g * 8 + 4];
            // B column pairs, read pre-packed straight from smem
            ulonglong2 bv0 = *(const ulonglong2*)&ws[k * 128 + c0];
            ulonglong2 bv1 = *(const ulonglong2*)&ws[k * 128 + c0 + 4];
            float a[8] = {a0.x, a0.y, a0.z, a0.w, a1.x, a1.y, a1.z, a1.w};
#pragma unroll
            for (int i = 0; i < 8; i++) {
                unsigned long long ad = pack2(a[i], a[i]);
                ffma2(acc2[i][0], ad, bv0.x);
                ffma2(acc2[i][1], ad, bv0.y);
                ffma2(acc2[i][2], ad, bv1.x);
                ffma2(acc2[i][3], ad, bv1.y);
            }
        }
    }

    // fold b1 into the PA half (cols < 64)
    float bias[8];
#pragma unroll
    for (int j = 0; j < 8; j++) bias[j] = (c0 < 64) ? b1[c0 + j] : 0.f;

#pragma unroll
    for (int i = 0; i < 8; i++) {
        int row = nb + g * 8 + i;
        if (row < n_nodes) {
            float v[8];
#pragma unroll
            for (int j = 0; j < 4; j++) unpack2(acc2[i][j], v[2 * j], v[2 * j + 1]);
            float4 o0 = make_float4(v[0] + bias[0], v[1] + bias[1],
                                    v[2] + bias[2], v[3] + bias[3]);
            float4 o1 = make_float4(v[4] + bias[4], v[5] + bias[5],
                                    v[6] + bias[6], v[7] + bias[7]);
            *(float4*)&g_P[(size_t)row * 128 + c0]     = o0;
            *(float4*)&g_P[(size_t)row * 128 + c0 + 4] = o1;
        }
    }
}

// ---------------------------------------------------------------------------
__device__ __forceinline__ int load_idx(const void* eidx, bool is64, long long off) {
    return is64 ? (int)((const long long*)eidx)[off] : ((const int*)eidx)[off];
}

// Edge kernel: warp per edge (grid-strided, persistent). Each lane holds one W2
// column packed as 32 f32x2 regs; h1 shared per-warp via smem as packed pairs.
// 2-deep pipeline: P rows prefetched one edge ahead, indices two ahead.
__global__ __launch_bounds__(256) void edge_kernel(
    const void* __restrict__ eidx,
    const float* __restrict__ W2, const float* __restrict__ b2,
    const float* __restrict__ W3, const float* __restrict__ b3,
    float* __restrict__ out, int E)
{
    __shared__ __align__(16) unsigned long long h1s[8][32];  // packed h1 pairs
    const int lane = threadIdx.x & 31;
    const int wid  = threadIdx.x >> 5;
    const int gw   = (blockIdx.x * blockDim.x + threadIdx.x) >> 5;
    const int GW   = (gridDim.x * blockDim.x) >> 5;

    // int64 vs int32 edge_index detection (warp-parallel, no extra kernel):
    // for LE int64 with values < 100000 every odd 32-bit word is zero.
    const int* ei32 = (const int*)eidx;
    int oddw = ei32[2 * lane + 1] | ei32[2 * lane + 65];
    const bool is64 = (__ballot_sync(0xffffffffu, oddw != 0) == 0u);

    // per-lane W2 column, packed along k: w2p[k2] = (W2[2k2][lane], W2[2k2+1][lane])
    unsigned long long w2p[32];
#pragma unroll
    for (int k2 = 0; k2 < 32; k2++)
        w2p[k2] = pack2(W2[(2 * k2) * 32 + lane], W2[(2 * k2 + 1) * 32 + lane]);
    const float b2r = b2[lane];
    const float w3r = W3[lane];
    const float b3v = b3[0];

    const float* __restrict__ P = g_P;

    int e = gw;
    int i0 = 0, j0 = 0;
    if (e < E) { i0 = load_idx(eidx, is64, e); j0 = load_idx(eidx, is64, (long long)E + e); }
    float2 pa = *(const float2*)(P + (size_t)i0 * 128 + 2 * lane);
    float2 pb = *(const float2*)(P + (size_t)j0 * 128 + 64 + 2 * lane);

    int en = e + GW;
    int i1 = 0, j1 = 0;
    if (en < E) { i1 = load_idx(eidx, is64, en); j1 = load_idx(eidx, is64, (long long)E + en); }

    while (e < E) {
        // prefetch P rows for next edge
        float2 npa = *(const float2*)(P + (size_t)i1 * 128 + 2 * lane);
        float2 npb = *(const float2*)(P + (size_t)j1 * 128 + 64 + 2 * lane);
        // prefetch indices two edges ahead
        int e2 = en + GW;
        int i2 = 0, j2 = 0;
        if (e2 < E) { i2 = load_idx(eidx, is64, e2); j2 = load_idx(eidx, is64, (long long)E + e2); }

        // layer 1: add + relu (b1 folded into P's first half already)
        float hx = fmaxf(pa.x + pb.x, 0.f);
        float hy = fmaxf(pa.y + pb.y, 0.f);
        h1s[wid][lane] = pack2(hx, hy);
        __syncwarp();

        // layer 2: acc2 = sum over 32 k-pairs of h-pair * w-pair  (FFMA2)
        unsigned long long acc2 = pack2(b2r, 0.f);
        const ulonglong2* hp = (const ulonglong2*)h1s[wid];
#pragma unroll
        for (int k4 = 0; k4 < 16; k4++) {
            ulonglong2 h = hp[k4];
            ffma2(acc2, h.x, w2p[2 * k4]);
            ffma2(acc2, h.y, w2p[2 * k4 + 1]);
        }
        __syncwarp();

        // layer 3 + sigmoid
        float alo, ahi;
        unpack2(acc2, alo, ahi);
        float h2 = fmaxf(alo + ahi, 0.f);
        float p  = h2 * w3r;
        p += __shfl_xor_sync(0xffffffffu, p, 16);
        p += __shfl_xor_sync(0xffffffffu, p, 8);
        p += __shfl_xor_sync(0xffffffffu, p, 4);
        p += __shfl_xor_sync(0xffffffffu, p, 2);
        p += __shfl_xor_sync(0xffffffffu, p, 1);
        if (lane == 0) {
            float logit = p + b3v;
            out[e] = __fdividef(1.f, 1.f + __expf(-logit));
        }

        // rotate pipeline
        pa = npa; pb = npb;
        i1 = i2; j1 = j2;
        e = en; en = e2;
    }
}

// ---------------------------------------------------------------------------
extern "C" void kernel_launch(void* const* d_in, const int* in_sizes, int n_in,
                              void* d_out, int out_size)
{
    const float* z  = (const float*)d_in[0];
    const void*  ei = d_in[1];
    const float* W1 = (const float*)d_in[2];
    const float* b1 = (const float*)d_in[3];
    const float* W2 = (const float*)d_in[4];
    const float* b2 = (const float*)d_in[5];
    const float* W3 = (const float*)d_in[6];
    const float* b3 = (const float*)d_in[7];
    float* out = (float*)d_out;

    int n_nodes = in_sizes[0] / INDIM;
    if (n_nodes > MAX_NODES) n_nodes = MAX_NODES;
    int E = out_size;  // one output per edge

    int gblocks = (n_nodes + 127) / 128;
    precompute_kernel<<<gblocks, 256>>>(z, W1, b1, n_nodes);
    edge_kernel<<<296, 256>>>(ei, W2, b2, W3, b3, out, E);
}